// round 10
// baseline (speedup 1.0000x reference)
#include <cuda_runtime.h>
#include <cstdint>

// ---------------------------------------------------------------------------
// GaussSpatialConv: out[i,:] = softmax_j( -||x_i - y_j||^2 / (2*sigma^2) ) @ fea
// B=1, N=M=12288, D=16, sigma=0.1.
//
// Strategy:
//   k_prep : pack y into float4 rows, negated (so dx = x + (-y) via add.f32x2)
//   k_min  : partial min_j d2 per query over M/SPL chunk   -> pmin[SPL][N]
//   k_acc  : with global min (read from pmin), accumulate
//            s = sum exp2(C*(d2-mind)), acc = sum p*fea    -> ps/pacc partials
//   k_norm : reduce partials over SPL, out = acc/s
//
// Shift by global per-query min d2 => max logit term is exp2(0)=1, so s >= 1
// always (no 0/0), partials combine by plain addition (deterministic).
// Inner loops use packed f32x2 FMA (2 queries per thread) to halve the
// FFMA-pipe instruction count, which is the binding resource.
// ---------------------------------------------------------------------------

typedef unsigned long long ull;

#define TPB 128      // threads per CTA in the heavy kernels
#define QPT 2        // queries per thread (packed into f32x2 lanes)
#define SPL 12       // splits of the M (j) dimension
#define DD  16       // feature dim (fixed for this problem)

// 32 MB static scratch (no allocations allowed). Layout computed at launch.
__device__ __align__(256) float g_scratch[8u << 20];

// ---- f32x2 helpers (Blackwell packed fp32) --------------------------------
__device__ __forceinline__ ull pk2(float lo, float hi) {
    ull r; asm("mov.b64 %0, {%1, %2};" : "=l"(r) : "f"(lo), "f"(hi)); return r;
}
__device__ __forceinline__ void upk2(ull v, float& lo, float& hi) {
    asm("mov.b64 {%0, %1}, %2;" : "=f"(lo), "=f"(hi) : "l"(v));
}
__device__ __forceinline__ ull add2(ull a, ull b) {
    ull r; asm("add.rn.f32x2 %0, %1, %2;" : "=l"(r) : "l"(a), "l"(b)); return r;
}
__device__ __forceinline__ ull mul2(ull a, ull b) {
    ull r; asm("mul.rn.f32x2 %0, %1, %2;" : "=l"(r) : "l"(a), "l"(b)); return r;
}
__device__ __forceinline__ ull fma2(ull a, ull b, ull c) {
    ull r; asm("fma.rn.f32x2 %0, %1, %2, %3;" : "=l"(r) : "l"(a), "l"(b), "l"(c)); return r;
}
// MUFU.EX2 — hardware exp2 approximation (~2 ulp; args are <= 0 here)
__device__ __forceinline__ float ex2(float a) {
    float r; asm("ex2.approx.ftz.f32 %0, %1;" : "=f"(r) : "f"(a)); return r;
}

// ---- k_prep: y4[j] = (-y0, -y1, -y2, 0) ------------------------------------
__global__ void k_prep(const float* __restrict__ y, long long off_y4, int M) {
    float4* y4 = reinterpret_cast<float4*>(g_scratch + off_y4);
    int j = blockIdx.x * blockDim.x + threadIdx.x;
    if (j < M) {
        float a = y[3 * j], b = y[3 * j + 1], c = y[3 * j + 2];
        y4[j] = make_float4(-a, -b, -c, 0.0f);
    }
}

// ---- k_min: partial min of d2 over this CTA's j-chunk ----------------------
__global__ void __launch_bounds__(TPB) k_min(
    const float* __restrict__ x,
    long long off_y4, long long off_pmin,
    int N, int M, int CH)
{
    const float4* __restrict__ y4 = reinterpret_cast<const float4*>(g_scratch + off_y4);
    float* __restrict__ pmin = g_scratch + off_pmin;

    int s  = blockIdx.x % SPL;
    int qb = blockIdx.x / SPL;
    int i0 = (qb * TPB + threadIdx.x) * QPT;
    int i1 = i0 + 1;
    int a0 = min(i0, N - 1), a1 = min(i1, N - 1);

    ull xx = pk2(x[3 * a0],     x[3 * a1]);
    ull xy = pk2(x[3 * a0 + 1], x[3 * a1 + 1]);
    ull xz = pk2(x[3 * a0 + 2], x[3 * a1 + 2]);

    int j0 = s * CH;
    int j1 = min(M, j0 + CH);
    float m0 = 3.4e38f, m1 = 3.4e38f;

    #pragma unroll 4
    for (int j = j0; j < j1; ++j) {
        float4 yv = y4[j];
        ull dx = add2(xx, pk2(yv.x, yv.x));
        ull dy = add2(xy, pk2(yv.y, yv.y));
        ull dz = add2(xz, pk2(yv.z, yv.z));
        ull d2 = mul2(dx, dx);
        d2 = fma2(dy, dy, d2);
        d2 = fma2(dz, dz, d2);
        float d20, d21; upk2(d2, d20, d21);
        m0 = fminf(m0, d20);
        m1 = fminf(m1, d21);
    }
    if (i0 < N) pmin[(size_t)s * N + i0] = m0;
    if (i1 < N) pmin[(size_t)s * N + i1] = m1;
}

// ---- k_acc: partial softmax numerator/denominator --------------------------
__global__ void __launch_bounds__(TPB) k_acc(
    const float* __restrict__ x,
    const ulonglong2* __restrict__ fea,   // M rows x 4 x ulonglong2 (= 16 floats)
    long long off_y4, long long off_pmin, long long off_ps, long long off_pacc,
    int N, int M, int CH)
{
    const float Cc = -72.13475204444817f;  // -log2(e) / (2 * 0.1^2)

    const float4* __restrict__ y4 = reinterpret_cast<const float4*>(g_scratch + off_y4);
    const float* __restrict__ pmin = g_scratch + off_pmin;
    float* __restrict__ ps   = g_scratch + off_ps;
    float* __restrict__ pacc = g_scratch + off_pacc;

    int s  = blockIdx.x % SPL;
    int qb = blockIdx.x / SPL;
    int i0 = (qb * TPB + threadIdx.x) * QPT;
    int i1 = i0 + 1;
    int a0 = min(i0, N - 1), a1 = min(i1, N - 1);

    ull xx = pk2(x[3 * a0],     x[3 * a1]);
    ull xy = pk2(x[3 * a0 + 1], x[3 * a1 + 1]);
    ull xz = pk2(x[3 * a0 + 2], x[3 * a1 + 2]);

    // global min d2 per query (reduce the SPL partials)
    float md0 = 3.4e38f, md1 = 3.4e38f;
    #pragma unroll
    for (int sp = 0; sp < SPL; ++sp) {
        md0 = fminf(md0, pmin[(size_t)sp * N + a0]);
        md1 = fminf(md1, pmin[(size_t)sp * N + a1]);
    }
    ull C2 = pk2(Cc, Cc);
    ull K2 = pk2(-Cc * md0, -Cc * md1);   // arg = C*d2 + K = C*(d2 - mind) <= 0

    ull acc0[8], acc1[8];
    #pragma unroll
    for (int k = 0; k < 8; ++k) { acc0[k] = 0ull; acc1[k] = 0ull; }
    float s0 = 0.0f, s1 = 0.0f;

    int j0 = s * CH;
    int j1 = min(M, j0 + CH);

    #pragma unroll 2
    for (int j = j0; j < j1; ++j) {
        float4 yv = y4[j];
        // identical d2 sequence to k_min -> arg <= 0 bitwise-guaranteed
        ull dx = add2(xx, pk2(yv.x, yv.x));
        ull dy = add2(xy, pk2(yv.y, yv.y));
        ull dz = add2(xz, pk2(yv.z, yv.z));
        ull d2 = mul2(dx, dx);
        d2 = fma2(dy, dy, d2);
        d2 = fma2(dz, dz, d2);
        ull arg = fma2(d2, C2, K2);
        float g0, g1; upk2(arg, g0, g1);
        float p0 = ex2(g0);
        float p1 = ex2(g1);
        s0 += p0;
        s1 += p1;
        ull pp0 = pk2(p0, p0);
        ull pp1 = pk2(p1, p1);

        const ulonglong2* fr = fea + (size_t)j * 4;
        ulonglong2 f0 = fr[0];
        ulonglong2 f1 = fr[1];
        ulonglong2 f2 = fr[2];
        ulonglong2 f3 = fr[3];
        acc0[0] = fma2(pp0, f0.x, acc0[0]);  acc1[0] = fma2(pp1, f0.x, acc1[0]);
        acc0[1] = fma2(pp0, f0.y, acc0[1]);  acc1[1] = fma2(pp1, f0.y, acc1[1]);
        acc0[2] = fma2(pp0, f1.x, acc0[2]);  acc1[2] = fma2(pp1, f1.x, acc1[2]);
        acc0[3] = fma2(pp0, f1.y, acc0[3]);  acc1[3] = fma2(pp1, f1.y, acc1[3]);
        acc0[4] = fma2(pp0, f2.x, acc0[4]);  acc1[4] = fma2(pp1, f2.x, acc1[4]);
        acc0[5] = fma2(pp0, f2.y, acc0[5]);  acc1[5] = fma2(pp1, f2.y, acc1[5]);
        acc0[6] = fma2(pp0, f3.x, acc0[6]);  acc1[6] = fma2(pp1, f3.x, acc1[6]);
        acc0[7] = fma2(pp0, f3.y, acc0[7]);  acc1[7] = fma2(pp1, f3.y, acc1[7]);
    }

    if (i0 < N) {
        ps[(size_t)s * N + i0] = s0;
        float4* dst = reinterpret_cast<float4*>(pacc + ((size_t)s * N + i0) * DD);
        #pragma unroll
        for (int k = 0; k < 4; ++k) {
            float lo0, hi0, lo1, hi1;
            upk2(acc0[2 * k],     lo0, hi0);
            upk2(acc0[2 * k + 1], lo1, hi1);
            dst[k] = make_float4(lo0, hi0, lo1, hi1);
        }
    }
    if (i1 < N) {
        ps[(size_t)s * N + i1] = s1;
        float4* dst = reinterpret_cast<float4*>(pacc + ((size_t)s * N + i1) * DD);
        #pragma unroll
        for (int k = 0; k < 4; ++k) {
            float lo0, hi0, lo1, hi1;
            upk2(acc1[2 * k],     lo0, hi0);
            upk2(acc1[2 * k + 1], lo1, hi1);
            dst[k] = make_float4(lo0, hi0, lo1, hi1);
        }
    }
}

// ---- k_norm: reduce over splits and normalize ------------------------------
__global__ void k_norm(long long off_ps, long long off_pacc,
                       float* __restrict__ out, int N)
{
    const float* __restrict__ ps   = g_scratch + off_ps;
    const float* __restrict__ pacc = g_scratch + off_pacc;
    int idx = blockIdx.x * blockDim.x + threadIdx.x;
    if (idx >= N * DD) return;
    int i = idx / DD;
    int d = idx % DD;
    float st = 0.0f, at = 0.0f;
    #pragma unroll
    for (int sp = 0; sp < SPL; ++sp) {
        st += ps[(size_t)sp * N + i];
        at += pacc[((size_t)sp * N + i) * DD + d];
    }
    out[idx] = at / st;
}

// ---------------------------------------------------------------------------
extern "C" void kernel_launch(void* const* d_in, const int* in_sizes, int n_in,
                              void* d_out, int out_size) {
    const float* x   = (const float*)d_in[0];   // [N,3]
    const float* y   = (const float*)d_in[1];   // [M,3]
    const float* fea = (const float*)d_in[2];   // [M,16]
    float* out = (float*)d_out;                 // [N,16]

    int N = in_sizes[0] / 3;
    int M = in_sizes[1] / 3;

    auto r4 = [](long long v) { return (v + 3) & ~3LL; };
    long long off_y4   = 0;
    long long off_pmin = r4(off_y4 + 4LL * M);
    long long off_ps   = r4(off_pmin + (long long)SPL * N);
    long long off_pacc = r4(off_ps + (long long)SPL * N);
    // total: 4M + 2*SPL*N + SPL*N*16  ~= 3.6M floats << 8M capacity

    int CH = (M + SPL - 1) / SPL;                 // j-chunk per split
    int QB = (N + TPB * QPT - 1) / (TPB * QPT);   // query blocks

    k_prep<<<(M + 255) / 256, 256>>>(y, off_y4, M);
    k_min<<<QB * SPL, TPB>>>(x, off_y4, off_pmin, N, M, CH);
    k_acc<<<QB * SPL, TPB>>>(x, (const ulonglong2*)fea,
                             off_y4, off_pmin, off_ps, off_pacc, N, M, CH);
    k_norm<<<(N * DD + 255) / 256, 256>>>(off_ps, off_pacc, out, N);
}

// round 11
// speedup vs baseline: 1.0595x; 1.0595x over previous
#include <cuda_runtime.h>
#include <cstdint>

// ---------------------------------------------------------------------------
// GaussSpatialConv: out[i,:] = softmax_j( -||x_i - y_j||^2 / (2*sigma^2) ) @ fea
// B=1, N=M=12288, D=16, sigma=0.1.
//
//   k_prep : pack y into float4 rows, negated
//   k_min  : partial min_j d2 per query over M/SPL chunk   -> pmin[SPL][N]
//   k_acc  : s = sum exp2(C*(d2-mind)), acc = sum p*fea    -> ps/pacc partials
//   k_norm : reduce partials over SPL, out = acc/s
//
// R10 change: SPL 12 -> 24. Per-CTA j-chunk working set = 512*(64+16)B = 40KB,
// so ~5 resident CTAs/SM (200KB) fit L1 (228KB). R9's 80KB/CTA thrashed L1 and
// pushed every hot-loop load to L2 (~240 cyc) -> measured 405us vs ~102us FMA
// floor. L1-resident, FMA (11.5 SM-cyc/iter) and LSU (9.1) become the binders.
// ---------------------------------------------------------------------------

typedef unsigned long long ull;

#define TPB 128      // threads per CTA in the heavy kernels
#define QPT 2        // queries per thread (packed into f32x2 lanes)
#define SPL 24       // splits of the M (j) dimension (CH = 12288/24 = 512)
#define DD  16       // feature dim (fixed for this problem)

// 32 MB static scratch (no allocations allowed). Layout computed at launch.
__device__ __align__(256) float g_scratch[8u << 20];

// ---- f32x2 helpers (Blackwell packed fp32) --------------------------------
__device__ __forceinline__ ull pk2(float lo, float hi) {
    ull r; asm("mov.b64 %0, {%1, %2};" : "=l"(r) : "f"(lo), "f"(hi)); return r;
}
__device__ __forceinline__ void upk2(ull v, float& lo, float& hi) {
    asm("mov.b64 {%0, %1}, %2;" : "=f"(lo), "=f"(hi) : "l"(v));
}
__device__ __forceinline__ ull add2(ull a, ull b) {
    ull r; asm("add.rn.f32x2 %0, %1, %2;" : "=l"(r) : "l"(a), "l"(b)); return r;
}
__device__ __forceinline__ ull mul2(ull a, ull b) {
    ull r; asm("mul.rn.f32x2 %0, %1, %2;" : "=l"(r) : "l"(a), "l"(b)); return r;
}
__device__ __forceinline__ ull fma2(ull a, ull b, ull c) {
    ull r; asm("fma.rn.f32x2 %0, %1, %2, %3;" : "=l"(r) : "l"(a), "l"(b), "l"(c)); return r;
}
// MUFU.EX2 — hardware exp2 approximation (~2 ulp; args are <= 0 here)
__device__ __forceinline__ float ex2(float a) {
    float r; asm("ex2.approx.ftz.f32 %0, %1;" : "=f"(r) : "f"(a)); return r;
}

// ---- k_prep: y4[j] = (-y0, -y1, -y2, 0) ------------------------------------
__global__ void k_prep(const float* __restrict__ y, long long off_y4, int M) {
    float4* y4 = reinterpret_cast<float4*>(g_scratch + off_y4);
    int j = blockIdx.x * blockDim.x + threadIdx.x;
    if (j < M) {
        float a = y[3 * j], b = y[3 * j + 1], c = y[3 * j + 2];
        y4[j] = make_float4(-a, -b, -c, 0.0f);
    }
}

// ---- k_min: partial min of d2 over this CTA's j-chunk ----------------------
__global__ void __launch_bounds__(TPB) k_min(
    const float* __restrict__ x,
    long long off_y4, long long off_pmin,
    int N, int M, int CH)
{
    const float4* __restrict__ y4 = reinterpret_cast<const float4*>(g_scratch + off_y4);
    float* __restrict__ pmin = g_scratch + off_pmin;

    int s  = blockIdx.x % SPL;
    int qb = blockIdx.x / SPL;
    int i0 = (qb * TPB + threadIdx.x) * QPT;
    int i1 = i0 + 1;
    int a0 = min(i0, N - 1), a1 = min(i1, N - 1);

    ull xx = pk2(x[3 * a0],     x[3 * a1]);
    ull xy = pk2(x[3 * a0 + 1], x[3 * a1 + 1]);
    ull xz = pk2(x[3 * a0 + 2], x[3 * a1 + 2]);

    int j0 = s * CH;
    int j1 = min(M, j0 + CH);
    float m0 = 3.4e38f, m1 = 3.4e38f;

    #pragma unroll 4
    for (int j = j0; j < j1; ++j) {
        float4 yv = y4[j];
        ull dx = add2(xx, pk2(yv.x, yv.x));
        ull dy = add2(xy, pk2(yv.y, yv.y));
        ull dz = add2(xz, pk2(yv.z, yv.z));
        ull d2 = mul2(dx, dx);
        d2 = fma2(dy, dy, d2);
        d2 = fma2(dz, dz, d2);
        float d20, d21; upk2(d2, d20, d21);
        m0 = fminf(m0, d20);
        m1 = fminf(m1, d21);
    }
    if (i0 < N) pmin[(size_t)s * N + i0] = m0;
    if (i1 < N) pmin[(size_t)s * N + i1] = m1;
}

// ---- k_acc: partial softmax numerator/denominator --------------------------
__global__ void __launch_bounds__(TPB) k_acc(
    const float* __restrict__ x,
    const ulonglong2* __restrict__ fea,   // M rows x 4 x ulonglong2 (= 16 floats)
    long long off_y4, long long off_pmin, long long off_ps, long long off_pacc,
    int N, int M, int CH)
{
    const float Cc = -72.13475204444817f;  // -log2(e) / (2 * 0.1^2)

    const float4* __restrict__ y4 = reinterpret_cast<const float4*>(g_scratch + off_y4);
    const float* __restrict__ pmin = g_scratch + off_pmin;
    float* __restrict__ ps   = g_scratch + off_ps;
    float* __restrict__ pacc = g_scratch + off_pacc;

    int s  = blockIdx.x % SPL;
    int qb = blockIdx.x / SPL;
    int i0 = (qb * TPB + threadIdx.x) * QPT;
    int i1 = i0 + 1;
    int a0 = min(i0, N - 1), a1 = min(i1, N - 1);

    ull xx = pk2(x[3 * a0],     x[3 * a1]);
    ull xy = pk2(x[3 * a0 + 1], x[3 * a1 + 1]);
    ull xz = pk2(x[3 * a0 + 2], x[3 * a1 + 2]);

    // global min d2 per query (reduce the SPL partials)
    float md0 = 3.4e38f, md1 = 3.4e38f;
    #pragma unroll
    for (int sp = 0; sp < SPL; ++sp) {
        md0 = fminf(md0, pmin[(size_t)sp * N + a0]);
        md1 = fminf(md1, pmin[(size_t)sp * N + a1]);
    }
    ull C2 = pk2(Cc, Cc);
    ull K2 = pk2(-Cc * md0, -Cc * md1);   // arg = C*d2 + K = C*(d2 - mind) <= 0

    ull acc0[8], acc1[8];
    #pragma unroll
    for (int k = 0; k < 8; ++k) { acc0[k] = 0ull; acc1[k] = 0ull; }
    float s0 = 0.0f, s1 = 0.0f;

    int j0 = s * CH;
    int j1 = min(M, j0 + CH);

    #pragma unroll 2
    for (int j = j0; j < j1; ++j) {
        float4 yv = y4[j];
        // identical d2 sequence to k_min -> arg <= 0 bitwise-guaranteed
        ull dx = add2(xx, pk2(yv.x, yv.x));
        ull dy = add2(xy, pk2(yv.y, yv.y));
        ull dz = add2(xz, pk2(yv.z, yv.z));
        ull d2 = mul2(dx, dx);
        d2 = fma2(dy, dy, d2);
        d2 = fma2(dz, dz, d2);
        ull arg = fma2(d2, C2, K2);
        float g0, g1; upk2(arg, g0, g1);
        float p0 = ex2(g0);
        float p1 = ex2(g1);
        s0 += p0;
        s1 += p1;
        ull pp0 = pk2(p0, p0);
        ull pp1 = pk2(p1, p1);

        const ulonglong2* fr = fea + (size_t)j * 4;
        ulonglong2 f0 = fr[0];
        ulonglong2 f1 = fr[1];
        ulonglong2 f2 = fr[2];
        ulonglong2 f3 = fr[3];
        acc0[0] = fma2(pp0, f0.x, acc0[0]);  acc1[0] = fma2(pp1, f0.x, acc1[0]);
        acc0[1] = fma2(pp0, f0.y, acc0[1]);  acc1[1] = fma2(pp1, f0.y, acc1[1]);
        acc0[2] = fma2(pp0, f1.x, acc0[2]);  acc1[2] = fma2(pp1, f1.x, acc1[2]);
        acc0[3] = fma2(pp0, f1.y, acc0[3]);  acc1[3] = fma2(pp1, f1.y, acc1[3]);
        acc0[4] = fma2(pp0, f2.x, acc0[4]);  acc1[4] = fma2(pp1, f2.x, acc1[4]);
        acc0[5] = fma2(pp0, f2.y, acc0[5]);  acc1[5] = fma2(pp1, f2.y, acc1[5]);
        acc0[6] = fma2(pp0, f3.x, acc0[6]);  acc1[6] = fma2(pp1, f3.x, acc1[6]);
        acc0[7] = fma2(pp0, f3.y, acc0[7]);  acc1[7] = fma2(pp1, f3.y, acc1[7]);
    }

    if (i0 < N) {
        ps[(size_t)s * N + i0] = s0;
        float4* dst = reinterpret_cast<float4*>(pacc + ((size_t)s * N + i0) * DD);
        #pragma unroll
        for (int k = 0; k < 4; ++k) {
            float lo0, hi0, lo1, hi1;
            upk2(acc0[2 * k],     lo0, hi0);
            upk2(acc0[2 * k + 1], lo1, hi1);
            dst[k] = make_float4(lo0, hi0, lo1, hi1);
        }
    }
    if (i1 < N) {
        ps[(size_t)s * N + i1] = s1;
        float4* dst = reinterpret_cast<float4*>(pacc + ((size_t)s * N + i1) * DD);
        #pragma unroll
        for (int k = 0; k < 4; ++k) {
            float lo0, hi0, lo1, hi1;
            upk2(acc1[2 * k],     lo0, hi0);
            upk2(acc1[2 * k + 1], lo1, hi1);
            dst[k] = make_float4(lo0, hi0, lo1, hi1);
        }
    }
}

// ---- k_norm: reduce over splits and normalize ------------------------------
__global__ void k_norm(long long off_ps, long long off_pacc,
                       float* __restrict__ out, int N)
{
    const float* __restrict__ ps   = g_scratch + off_ps;
    const float* __restrict__ pacc = g_scratch + off_pacc;
    int idx = blockIdx.x * blockDim.x + threadIdx.x;
    if (idx >= N * DD) return;
    int i = idx / DD;
    int d = idx % DD;
    float st = 0.0f, at = 0.0f;
    #pragma unroll
    for (int sp = 0; sp < SPL; ++sp) {
        st += ps[(size_t)sp * N + i];
        at += pacc[((size_t)sp * N + i) * DD + d];
    }
    out[idx] = at / st;
}

// ---------------------------------------------------------------------------
extern "C" void kernel_launch(void* const* d_in, const int* in_sizes, int n_in,
                              void* d_out, int out_size) {
    const float* x   = (const float*)d_in[0];   // [N,3]
    const float* y   = (const float*)d_in[1];   // [M,3]
    const float* fea = (const float*)d_in[2];   // [M,16]
    float* out = (float*)d_out;                 // [N,16]

    int N = in_sizes[0] / 3;
    int M = in_sizes[1] / 3;

    auto r4 = [](long long v) { return (v + 3) & ~3LL; };
    long long off_y4   = 0;
    long long off_pmin = r4(off_y4 + 4LL * M);
    long long off_ps   = r4(off_pmin + (long long)SPL * N);
    long long off_pacc = r4(off_ps + (long long)SPL * N);
    // total: 4M + 2*SPL*N + SPL*N*16  ~= 5.4M floats < 8M capacity

    int CH = (M + SPL - 1) / SPL;                 // j-chunk per split (512)
    int QB = (N + TPB * QPT - 1) / (TPB * QPT);   // query blocks (48)

    k_prep<<<(M + 255) / 256, 256>>>(y, off_y4, M);
    k_min<<<QB * SPL, TPB>>>(x, off_y4, off_pmin, N, M, CH);
    k_acc<<<QB * SPL, TPB>>>(x, (const ulonglong2*)fea,
                             off_y4, off_pmin, off_ps, off_pacc, N, M, CH);
    k_norm<<<(N * DD + 255) / 256, 256>>>(off_ps, off_pacc, out, N);
}

// round 12
// speedup vs baseline: 1.0874x; 1.0263x over previous
#include <cuda_runtime.h>
#include <cstdint>

// ---------------------------------------------------------------------------
// GaussSpatialConv: out[i,:] = softmax_j( -||x_i - y_j||^2 / (2*sigma^2) ) @ fea
// B=1, N=M=12288, D=16, sigma=0.1.
//
//   k_prep : pack y into float4 rows, negated
//   k_min  : partial min_j d2 per query over M/SPL chunk   -> pmin[SPL][N]
//   k_acc  : s = sum exp2(C*(d2-mind)), acc = sum p*fea    -> ps/pacc partials
//   k_norm : reduce partials over SPL, out = acc/s
//
// R10 change: SPL 12 -> 24. Per-CTA j-chunk working set = 512*(64+16)B = 40KB,
// so ~5 resident CTAs/SM (200KB) fit L1 (228KB). R9's 80KB/CTA thrashed L1 and
// pushed every hot-loop load to L2 (~240 cyc) -> measured 405us vs ~102us FMA
// floor. L1-resident, FMA (11.5 SM-cyc/iter) and LSU (9.1) become the binders.
// ---------------------------------------------------------------------------

typedef unsigned long long ull;

#define TPB 128      // threads per CTA in the heavy kernels
#define QPT 2        // queries per thread (packed into f32x2 lanes)
#define SPL 24       // splits of the M (j) dimension (CH = 12288/24 = 512)
#define DD  16       // feature dim (fixed for this problem)

// 32 MB static scratch (no allocations allowed). Layout computed at launch.
__device__ __align__(256) float g_scratch[8u << 20];

// ---- f32x2 helpers (Blackwell packed fp32) --------------------------------
__device__ __forceinline__ ull pk2(float lo, float hi) {
    ull r; asm("mov.b64 %0, {%1, %2};" : "=l"(r) : "f"(lo), "f"(hi)); return r;
}
__device__ __forceinline__ void upk2(ull v, float& lo, float& hi) {
    asm("mov.b64 {%0, %1}, %2;" : "=f"(lo), "=f"(hi) : "l"(v));
}
__device__ __forceinline__ ull add2(ull a, ull b) {
    ull r; asm("add.rn.f32x2 %0, %1, %2;" : "=l"(r) : "l"(a), "l"(b)); return r;
}
__device__ __forceinline__ ull mul2(ull a, ull b) {
    ull r; asm("mul.rn.f32x2 %0, %1, %2;" : "=l"(r) : "l"(a), "l"(b)); return r;
}
__device__ __forceinline__ ull fma2(ull a, ull b, ull c) {
    ull r; asm("fma.rn.f32x2 %0, %1, %2, %3;" : "=l"(r) : "l"(a), "l"(b), "l"(c)); return r;
}
// MUFU.EX2 — hardware exp2 approximation (~2 ulp; args are <= 0 here)
__device__ __forceinline__ float ex2(float a) {
    float r; asm("ex2.approx.ftz.f32 %0, %1;" : "=f"(r) : "f"(a)); return r;
}

// ---- k_prep: y4[j] = (-y0, -y1, -y2, 0) ------------------------------------
__global__ void k_prep(const float* __restrict__ y, long long off_y4, int M) {
    float4* y4 = reinterpret_cast<float4*>(g_scratch + off_y4);
    int j = blockIdx.x * blockDim.x + threadIdx.x;
    if (j < M) {
        float a = y[3 * j], b = y[3 * j + 1], c = y[3 * j + 2];
        y4[j] = make_float4(-a, -b, -c, 0.0f);
    }
}

// ---- k_min: partial min of d2 over this CTA's j-chunk ----------------------
__global__ void __launch_bounds__(TPB) k_min(
    const float* __restrict__ x,
    long long off_y4, long long off_pmin,
    int N, int M, int CH)
{
    const float4* __restrict__ y4 = reinterpret_cast<const float4*>(g_scratch + off_y4);
    float* __restrict__ pmin = g_scratch + off_pmin;

    int s  = blockIdx.x % SPL;
    int qb = blockIdx.x / SPL;
    int i0 = (qb * TPB + threadIdx.x) * QPT;
    int i1 = i0 + 1;
    int a0 = min(i0, N - 1), a1 = min(i1, N - 1);

    ull xx = pk2(x[3 * a0],     x[3 * a1]);
    ull xy = pk2(x[3 * a0 + 1], x[3 * a1 + 1]);
    ull xz = pk2(x[3 * a0 + 2], x[3 * a1 + 2]);

    int j0 = s * CH;
    int j1 = min(M, j0 + CH);
    float m0 = 3.4e38f, m1 = 3.4e38f;

    #pragma unroll 4
    for (int j = j0; j < j1; ++j) {
        float4 yv = y4[j];
        ull dx = add2(xx, pk2(yv.x, yv.x));
        ull dy = add2(xy, pk2(yv.y, yv.y));
        ull dz = add2(xz, pk2(yv.z, yv.z));
        ull d2 = mul2(dx, dx);
        d2 = fma2(dy, dy, d2);
        d2 = fma2(dz, dz, d2);
        float d20, d21; upk2(d2, d20, d21);
        m0 = fminf(m0, d20);
        m1 = fminf(m1, d21);
    }
    if (i0 < N) pmin[(size_t)s * N + i0] = m0;
    if (i1 < N) pmin[(size_t)s * N + i1] = m1;
}

// ---- k_acc: partial softmax numerator/denominator --------------------------
__global__ void __launch_bounds__(TPB) k_acc(
    const float* __restrict__ x,
    const ulonglong2* __restrict__ fea,   // M rows x 4 x ulonglong2 (= 16 floats)
    long long off_y4, long long off_pmin, long long off_ps, long long off_pacc,
    int N, int M, int CH)
{
    const float Cc = -72.13475204444817f;  // -log2(e) / (2 * 0.1^2)

    const float4* __restrict__ y4 = reinterpret_cast<const float4*>(g_scratch + off_y4);
    const float* __restrict__ pmin = g_scratch + off_pmin;
    float* __restrict__ ps   = g_scratch + off_ps;
    float* __restrict__ pacc = g_scratch + off_pacc;

    int s  = blockIdx.x % SPL;
    int qb = blockIdx.x / SPL;
    int i0 = (qb * TPB + threadIdx.x) * QPT;
    int i1 = i0 + 1;
    int a0 = min(i0, N - 1), a1 = min(i1, N - 1);

    ull xx = pk2(x[3 * a0],     x[3 * a1]);
    ull xy = pk2(x[3 * a0 + 1], x[3 * a1 + 1]);
    ull xz = pk2(x[3 * a0 + 2], x[3 * a1 + 2]);

    // global min d2 per query (reduce the SPL partials)
    float md0 = 3.4e38f, md1 = 3.4e38f;
    #pragma unroll
    for (int sp = 0; sp < SPL; ++sp) {
        md0 = fminf(md0, pmin[(size_t)sp * N + a0]);
        md1 = fminf(md1, pmin[(size_t)sp * N + a1]);
    }
    ull C2 = pk2(Cc, Cc);
    ull K2 = pk2(-Cc * md0, -Cc * md1);   // arg = C*d2 + K = C*(d2 - mind) <= 0

    ull acc0[8], acc1[8];
    #pragma unroll
    for (int k = 0; k < 8; ++k) { acc0[k] = 0ull; acc1[k] = 0ull; }
    float s0 = 0.0f, s1 = 0.0f;

    int j0 = s * CH;
    int j1 = min(M, j0 + CH);

    #pragma unroll 2
    for (int j = j0; j < j1; ++j) {
        float4 yv = y4[j];
        // identical d2 sequence to k_min -> arg <= 0 bitwise-guaranteed
        ull dx = add2(xx, pk2(yv.x, yv.x));
        ull dy = add2(xy, pk2(yv.y, yv.y));
        ull dz = add2(xz, pk2(yv.z, yv.z));
        ull d2 = mul2(dx, dx);
        d2 = fma2(dy, dy, d2);
        d2 = fma2(dz, dz, d2);
        ull arg = fma2(d2, C2, K2);
        float g0, g1; upk2(arg, g0, g1);
        float p0 = ex2(g0);
        float p1 = ex2(g1);
        s0 += p0;
        s1 += p1;
        ull pp0 = pk2(p0, p0);
        ull pp1 = pk2(p1, p1);

        const ulonglong2* fr = fea + (size_t)j * 4;
        ulonglong2 f0 = fr[0];
        ulonglong2 f1 = fr[1];
        ulonglong2 f2 = fr[2];
        ulonglong2 f3 = fr[3];
        acc0[0] = fma2(pp0, f0.x, acc0[0]);  acc1[0] = fma2(pp1, f0.x, acc1[0]);
        acc0[1] = fma2(pp0, f0.y, acc0[1]);  acc1[1] = fma2(pp1, f0.y, acc1[1]);
        acc0[2] = fma2(pp0, f1.x, acc0[2]);  acc1[2] = fma2(pp1, f1.x, acc1[2]);
        acc0[3] = fma2(pp0, f1.y, acc0[3]);  acc1[3] = fma2(pp1, f1.y, acc1[3]);
        acc0[4] = fma2(pp0, f2.x, acc0[4]);  acc1[4] = fma2(pp1, f2.x, acc1[4]);
        acc0[5] = fma2(pp0, f2.y, acc0[5]);  acc1[5] = fma2(pp1, f2.y, acc1[5]);
        acc0[6] = fma2(pp0, f3.x, acc0[6]);  acc1[6] = fma2(pp1, f3.x, acc1[6]);
        acc0[7] = fma2(pp0, f3.y, acc0[7]);  acc1[7] = fma2(pp1, f3.y, acc1[7]);
    }

    if (i0 < N) {
        ps[(size_t)s * N + i0] = s0;
        float4* dst = reinterpret_cast<float4*>(pacc + ((size_t)s * N + i0) * DD);
        #pragma unroll
        for (int k = 0; k < 4; ++k) {
            float lo0, hi0, lo1, hi1;
            upk2(acc0[2 * k],     lo0, hi0);
            upk2(acc0[2 * k + 1], lo1, hi1);
            dst[k] = make_float4(lo0, hi0, lo1, hi1);
        }
    }
    if (i1 < N) {
        ps[(size_t)s * N + i1] = s1;
        float4* dst = reinterpret_cast<float4*>(pacc + ((size_t)s * N + i1) * DD);
        #pragma unroll
        for (int k = 0; k < 4; ++k) {
            float lo0, hi0, lo1, hi1;
            upk2(acc1[2 * k],     lo0, hi0);
            upk2(acc1[2 * k + 1], lo1, hi1);
            dst[k] = make_float4(lo0, hi0, lo1, hi1);
        }
    }
}

// ---- k_norm: reduce over splits and normalize ------------------------------
__global__ void k_norm(long long off_ps, long long off_pacc,
                       float* __restrict__ out, int N)
{
    const float* __restrict__ ps   = g_scratch + off_ps;
    const float* __restrict__ pacc = g_scratch + off_pacc;
    int idx = blockIdx.x * blockDim.x + threadIdx.x;
    if (idx >= N * DD) return;
    int i = idx / DD;
    int d = idx % DD;
    float st = 0.0f, at = 0.0f;
    #pragma unroll
    for (int sp = 0; sp < SPL; ++sp) {
        st += ps[(size_t)sp * N + i];
        at += pacc[((size_t)sp * N + i) * DD + d];
    }
    out[idx] = at / st;
}

// ---------------------------------------------------------------------------
extern "C" void kernel_launch(void* const* d_in, const int* in_sizes, int n_in,
                              void* d_out, int out_size) {
    const float* x   = (const float*)d_in[0];   // [N,3]
    const float* y   = (const float*)d_in[1];   // [M,3]
    const float* fea = (const float*)d_in[2];   // [M,16]
    float* out = (float*)d_out;                 // [N,16]

    int N = in_sizes[0] / 3;
    int M = in_sizes[1] / 3;

    auto r4 = [](long long v) { return (v + 3) & ~3LL; };
    long long off_y4   = 0;
    long long off_pmin = r4(off_y4 + 4LL * M);
    long long off_ps   = r4(off_pmin + (long long)SPL * N);
    long long off_pacc = r4(off_ps + (long long)SPL * N);
    // total: 4M + 2*SPL*N + SPL*N*16  ~= 5.4M floats < 8M capacity

    int CH = (M + SPL - 1) / SPL;                 // j-chunk per split (512)
    int QB = (N + TPB * QPT - 1) / (TPB * QPT);   // query blocks (48)

    k_prep<<<(M + 255) / 256, 256>>>(y, off_y4, M);
    k_min<<<QB * SPL, TPB>>>(x, off_y4, off_pmin, N, M, CH);
    k_acc<<<QB * SPL, TPB>>>(x, (const ulonglong2*)fea,
                             off_y4, off_pmin, off_ps, off_pacc, N, M, CH);
    k_norm<<<(N * DD + 255) / 256, 256>>>(off_ps, off_pacc, out, N);
}

// round 13
// speedup vs baseline: 1.1094x; 1.0203x over previous
#include <cuda_runtime.h>
#include <cstdint>

// ---------------------------------------------------------------------------
// GaussSpatialConv: out[i,:] = softmax_j( -||x_i - y_j||^2 / (2*sigma^2) ) @ fea
// B=1, N=M=12288, D=16, sigma=0.1.
//
//   k_prep : pack y into float4 rows, negated
//   k_min  : partial min_j d2 per query over M/SPL chunk   -> pmin[SPL][N]
//   k_acc  : s = sum exp2(C*(d2-mind)), acc = sum p*fea    -> ps/pacc partials
//   k_norm : reduce partials over SPL, out = acc/s
//
// R10 change: SPL 12 -> 24. Per-CTA j-chunk working set = 512*(64+16)B = 40KB,
// so ~5 resident CTAs/SM (200KB) fit L1 (228KB). R9's 80KB/CTA thrashed L1 and
// pushed every hot-loop load to L2 (~240 cyc) -> measured 405us vs ~102us FMA
// floor. L1-resident, FMA (11.5 SM-cyc/iter) and LSU (9.1) become the binders.
// ---------------------------------------------------------------------------

typedef unsigned long long ull;

#define TPB 128      // threads per CTA in the heavy kernels
#define QPT 2        // queries per thread (packed into f32x2 lanes)
#define SPL 24       // splits of the M (j) dimension (CH = 12288/24 = 512)
#define DD  16       // feature dim (fixed for this problem)

// 32 MB static scratch (no allocations allowed). Layout computed at launch.
__device__ __align__(256) float g_scratch[8u << 20];

// ---- f32x2 helpers (Blackwell packed fp32) --------------------------------
__device__ __forceinline__ ull pk2(float lo, float hi) {
    ull r; asm("mov.b64 %0, {%1, %2};" : "=l"(r) : "f"(lo), "f"(hi)); return r;
}
__device__ __forceinline__ void upk2(ull v, float& lo, float& hi) {
    asm("mov.b64 {%0, %1}, %2;" : "=f"(lo), "=f"(hi) : "l"(v));
}
__device__ __forceinline__ ull add2(ull a, ull b) {
    ull r; asm("add.rn.f32x2 %0, %1, %2;" : "=l"(r) : "l"(a), "l"(b)); return r;
}
__device__ __forceinline__ ull mul2(ull a, ull b) {
    ull r; asm("mul.rn.f32x2 %0, %1, %2;" : "=l"(r) : "l"(a), "l"(b)); return r;
}
__device__ __forceinline__ ull fma2(ull a, ull b, ull c) {
    ull r; asm("fma.rn.f32x2 %0, %1, %2, %3;" : "=l"(r) : "l"(a), "l"(b), "l"(c)); return r;
}
// MUFU.EX2 — hardware exp2 approximation (~2 ulp; args are <= 0 here)
__device__ __forceinline__ float ex2(float a) {
    float r; asm("ex2.approx.ftz.f32 %0, %1;" : "=f"(r) : "f"(a)); return r;
}

// ---- k_prep: y4[j] = (-y0, -y1, -y2, 0) ------------------------------------
__global__ void k_prep(const float* __restrict__ y, long long off_y4, int M) {
    float4* y4 = reinterpret_cast<float4*>(g_scratch + off_y4);
    int j = blockIdx.x * blockDim.x + threadIdx.x;
    if (j < M) {
        float a = y[3 * j], b = y[3 * j + 1], c = y[3 * j + 2];
        y4[j] = make_float4(-a, -b, -c, 0.0f);
    }
}

// ---- k_min: partial min of d2 over this CTA's j-chunk ----------------------
__global__ void __launch_bounds__(TPB) k_min(
    const float* __restrict__ x,
    long long off_y4, long long off_pmin,
    int N, int M, int CH)
{
    const float4* __restrict__ y4 = reinterpret_cast<const float4*>(g_scratch + off_y4);
    float* __restrict__ pmin = g_scratch + off_pmin;

    int s  = blockIdx.x % SPL;
    int qb = blockIdx.x / SPL;
    int i0 = (qb * TPB + threadIdx.x) * QPT;
    int i1 = i0 + 1;
    int a0 = min(i0, N - 1), a1 = min(i1, N - 1);

    ull xx = pk2(x[3 * a0],     x[3 * a1]);
    ull xy = pk2(x[3 * a0 + 1], x[3 * a1 + 1]);
    ull xz = pk2(x[3 * a0 + 2], x[3 * a1 + 2]);

    int j0 = s * CH;
    int j1 = min(M, j0 + CH);
    float m0 = 3.4e38f, m1 = 3.4e38f;

    #pragma unroll 4
    for (int j = j0; j < j1; ++j) {
        float4 yv = y4[j];
        ull dx = add2(xx, pk2(yv.x, yv.x));
        ull dy = add2(xy, pk2(yv.y, yv.y));
        ull dz = add2(xz, pk2(yv.z, yv.z));
        ull d2 = mul2(dx, dx);
        d2 = fma2(dy, dy, d2);
        d2 = fma2(dz, dz, d2);
        float d20, d21; upk2(d2, d20, d21);
        m0 = fminf(m0, d20);
        m1 = fminf(m1, d21);
    }
    if (i0 < N) pmin[(size_t)s * N + i0] = m0;
    if (i1 < N) pmin[(size_t)s * N + i1] = m1;
}

// ---- k_acc: partial softmax numerator/denominator --------------------------
__global__ void __launch_bounds__(TPB) k_acc(
    const float* __restrict__ x,
    const ulonglong2* __restrict__ fea,   // M rows x 4 x ulonglong2 (= 16 floats)
    long long off_y4, long long off_pmin, long long off_ps, long long off_pacc,
    int N, int M, int CH)
{
    const float Cc = -72.13475204444817f;  // -log2(e) / (2 * 0.1^2)

    const float4* __restrict__ y4 = reinterpret_cast<const float4*>(g_scratch + off_y4);
    const float* __restrict__ pmin = g_scratch + off_pmin;
    float* __restrict__ ps   = g_scratch + off_ps;
    float* __restrict__ pacc = g_scratch + off_pacc;

    int s  = blockIdx.x % SPL;
    int qb = blockIdx.x / SPL;
    int i0 = (qb * TPB + threadIdx.x) * QPT;
    int i1 = i0 + 1;
    int a0 = min(i0, N - 1), a1 = min(i1, N - 1);

    ull xx = pk2(x[3 * a0],     x[3 * a1]);
    ull xy = pk2(x[3 * a0 + 1], x[3 * a1 + 1]);
    ull xz = pk2(x[3 * a0 + 2], x[3 * a1 + 2]);

    // global min d2 per query (reduce the SPL partials)
    float md0 = 3.4e38f, md1 = 3.4e38f;
    #pragma unroll
    for (int sp = 0; sp < SPL; ++sp) {
        md0 = fminf(md0, pmin[(size_t)sp * N + a0]);
        md1 = fminf(md1, pmin[(size_t)sp * N + a1]);
    }
    ull C2 = pk2(Cc, Cc);
    ull K2 = pk2(-Cc * md0, -Cc * md1);   // arg = C*d2 + K = C*(d2 - mind) <= 0

    ull acc0[8], acc1[8];
    #pragma unroll
    for (int k = 0; k < 8; ++k) { acc0[k] = 0ull; acc1[k] = 0ull; }
    float s0 = 0.0f, s1 = 0.0f;

    int j0 = s * CH;
    int j1 = min(M, j0 + CH);

    #pragma unroll 2
    for (int j = j0; j < j1; ++j) {
        float4 yv = y4[j];
        // identical d2 sequence to k_min -> arg <= 0 bitwise-guaranteed
        ull dx = add2(xx, pk2(yv.x, yv.x));
        ull dy = add2(xy, pk2(yv.y, yv.y));
        ull dz = add2(xz, pk2(yv.z, yv.z));
        ull d2 = mul2(dx, dx);
        d2 = fma2(dy, dy, d2);
        d2 = fma2(dz, dz, d2);
        ull arg = fma2(d2, C2, K2);
        float g0, g1; upk2(arg, g0, g1);
        float p0 = ex2(g0);
        float p1 = ex2(g1);
        s0 += p0;
        s1 += p1;
        ull pp0 = pk2(p0, p0);
        ull pp1 = pk2(p1, p1);

        const ulonglong2* fr = fea + (size_t)j * 4;
        ulonglong2 f0 = fr[0];
        ulonglong2 f1 = fr[1];
        ulonglong2 f2 = fr[2];
        ulonglong2 f3 = fr[3];
        acc0[0] = fma2(pp0, f0.x, acc0[0]);  acc1[0] = fma2(pp1, f0.x, acc1[0]);
        acc0[1] = fma2(pp0, f0.y, acc0[1]);  acc1[1] = fma2(pp1, f0.y, acc1[1]);
        acc0[2] = fma2(pp0, f1.x, acc0[2]);  acc1[2] = fma2(pp1, f1.x, acc1[2]);
        acc0[3] = fma2(pp0, f1.y, acc0[3]);  acc1[3] = fma2(pp1, f1.y, acc1[3]);
        acc0[4] = fma2(pp0, f2.x, acc0[4]);  acc1[4] = fma2(pp1, f2.x, acc1[4]);
        acc0[5] = fma2(pp0, f2.y, acc0[5]);  acc1[5] = fma2(pp1, f2.y, acc1[5]);
        acc0[6] = fma2(pp0, f3.x, acc0[6]);  acc1[6] = fma2(pp1, f3.x, acc1[6]);
        acc0[7] = fma2(pp0, f3.y, acc0[7]);  acc1[7] = fma2(pp1, f3.y, acc1[7]);
    }

    if (i0 < N) {
        ps[(size_t)s * N + i0] = s0;
        float4* dst = reinterpret_cast<float4*>(pacc + ((size_t)s * N + i0) * DD);
        #pragma unroll
        for (int k = 0; k < 4; ++k) {
            float lo0, hi0, lo1, hi1;
            upk2(acc0[2 * k],     lo0, hi0);
            upk2(acc0[2 * k + 1], lo1, hi1);
            dst[k] = make_float4(lo0, hi0, lo1, hi1);
        }
    }
    if (i1 < N) {
        ps[(size_t)s * N + i1] = s1;
        float4* dst = reinterpret_cast<float4*>(pacc + ((size_t)s * N + i1) * DD);
        #pragma unroll
        for (int k = 0; k < 4; ++k) {
            float lo0, hi0, lo1, hi1;
            upk2(acc1[2 * k],     lo0, hi0);
            upk2(acc1[2 * k + 1], lo1, hi1);
            dst[k] = make_float4(lo0, hi0, lo1, hi1);
        }
    }
}

// ---- k_norm: reduce over splits and normalize ------------------------------
__global__ void k_norm(long long off_ps, long long off_pacc,
                       float* __restrict__ out, int N)
{
    const float* __restrict__ ps   = g_scratch + off_ps;
    const float* __restrict__ pacc = g_scratch + off_pacc;
    int idx = blockIdx.x * blockDim.x + threadIdx.x;
    if (idx >= N * DD) return;
    int i = idx / DD;
    int d = idx % DD;
    float st = 0.0f, at = 0.0f;
    #pragma unroll
    for (int sp = 0; sp < SPL; ++sp) {
        st += ps[(size_t)sp * N + i];
        at += pacc[((size_t)sp * N + i) * DD + d];
    }
    out[idx] = at / st;
}

// ---------------------------------------------------------------------------
extern "C" void kernel_launch(void* const* d_in, const int* in_sizes, int n_in,
                              void* d_out, int out_size) {
    const float* x   = (const float*)d_in[0];   // [N,3]
    const float* y   = (const float*)d_in[1];   // [M,3]
    const float* fea = (const float*)d_in[2];   // [M,16]
    float* out = (float*)d_out;                 // [N,16]

    int N = in_sizes[0] / 3;
    int M = in_sizes[1] / 3;

    auto r4 = [](long long v) { return (v + 3) & ~3LL; };
    long long off_y4   = 0;
    long long off_pmin = r4(off_y4 + 4LL * M);
    long long off_ps   = r4(off_pmin + (long long)SPL * N);
    long long off_pacc = r4(off_ps + (long long)SPL * N);
    // total: 4M + 2*SPL*N + SPL*N*16  ~= 5.4M floats < 8M capacity

    int CH = (M + SPL - 1) / SPL;                 // j-chunk per split (512)
    int QB = (N + TPB * QPT - 1) / (TPB * QPT);   // query blocks (48)

    k_prep<<<(M + 255) / 256, 256>>>(y, off_y4, M);
    k_min<<<QB * SPL, TPB>>>(x, off_y4, off_pmin, N, M, CH);
    k_acc<<<QB * SPL, TPB>>>(x, (const ulonglong2*)fea,
                             off_y4, off_pmin, off_ps, off_pacc, N, M, CH);
    k_norm<<<(N * DD + 255) / 256, 256>>>(off_ps, off_pacc, out, N);
}

// round 14
// speedup vs baseline: 1.1097x; 1.0003x over previous
#include <cuda_runtime.h>
#include <cstdint>

// ---------------------------------------------------------------------------
// GaussSpatialConv: out[i,:] = softmax_j( -||x_i - y_j||^2 / (2*sigma^2) ) @ fea
// B=1, N=M=12288, D=16, sigma=0.1.
//
//   k_prep : pack y into float4 rows, negated
//   k_min  : partial min_j d2 per query over M/SPL chunk   -> pmin[SPL][N]
//   k_acc  : s = sum exp2(C*(d2-mind)), acc = sum p*fea    -> ps/pacc partials
//   k_norm : reduce partials over SPL, out = acc/s
//
// R10 change: SPL 12 -> 24. Per-CTA j-chunk working set = 512*(64+16)B = 40KB,
// so ~5 resident CTAs/SM (200KB) fit L1 (228KB). R9's 80KB/CTA thrashed L1 and
// pushed every hot-loop load to L2 (~240 cyc) -> measured 405us vs ~102us FMA
// floor. L1-resident, FMA (11.5 SM-cyc/iter) and LSU (9.1) become the binders.
// ---------------------------------------------------------------------------

typedef unsigned long long ull;

#define TPB 128      // threads per CTA in the heavy kernels
#define QPT 2        // queries per thread (packed into f32x2 lanes)
#define SPL 24       // splits of the M (j) dimension (CH = 12288/24 = 512)
#define DD  16       // feature dim (fixed for this problem)

// 32 MB static scratch (no allocations allowed). Layout computed at launch.
__device__ __align__(256) float g_scratch[8u << 20];

// ---- f32x2 helpers (Blackwell packed fp32) --------------------------------
__device__ __forceinline__ ull pk2(float lo, float hi) {
    ull r; asm("mov.b64 %0, {%1, %2};" : "=l"(r) : "f"(lo), "f"(hi)); return r;
}
__device__ __forceinline__ void upk2(ull v, float& lo, float& hi) {
    asm("mov.b64 {%0, %1}, %2;" : "=f"(lo), "=f"(hi) : "l"(v));
}
__device__ __forceinline__ ull add2(ull a, ull b) {
    ull r; asm("add.rn.f32x2 %0, %1, %2;" : "=l"(r) : "l"(a), "l"(b)); return r;
}
__device__ __forceinline__ ull mul2(ull a, ull b) {
    ull r; asm("mul.rn.f32x2 %0, %1, %2;" : "=l"(r) : "l"(a), "l"(b)); return r;
}
__device__ __forceinline__ ull fma2(ull a, ull b, ull c) {
    ull r; asm("fma.rn.f32x2 %0, %1, %2, %3;" : "=l"(r) : "l"(a), "l"(b), "l"(c)); return r;
}
// MUFU.EX2 — hardware exp2 approximation (~2 ulp; args are <= 0 here)
__device__ __forceinline__ float ex2(float a) {
    float r; asm("ex2.approx.ftz.f32 %0, %1;" : "=f"(r) : "f"(a)); return r;
}

// ---- k_prep: y4[j] = (-y0, -y1, -y2, 0) ------------------------------------
__global__ void k_prep(const float* __restrict__ y, long long off_y4, int M) {
    float4* y4 = reinterpret_cast<float4*>(g_scratch + off_y4);
    int j = blockIdx.x * blockDim.x + threadIdx.x;
    if (j < M) {
        float a = y[3 * j], b = y[3 * j + 1], c = y[3 * j + 2];
        y4[j] = make_float4(-a, -b, -c, 0.0f);
    }
}

// ---- k_min: partial min of d2 over this CTA's j-chunk ----------------------
__global__ void __launch_bounds__(TPB) k_min(
    const float* __restrict__ x,
    long long off_y4, long long off_pmin,
    int N, int M, int CH)
{
    const float4* __restrict__ y4 = reinterpret_cast<const float4*>(g_scratch + off_y4);
    float* __restrict__ pmin = g_scratch + off_pmin;

    int s  = blockIdx.x % SPL;
    int qb = blockIdx.x / SPL;
    int i0 = (qb * TPB + threadIdx.x) * QPT;
    int i1 = i0 + 1;
    int a0 = min(i0, N - 1), a1 = min(i1, N - 1);

    ull xx = pk2(x[3 * a0],     x[3 * a1]);
    ull xy = pk2(x[3 * a0 + 1], x[3 * a1 + 1]);
    ull xz = pk2(x[3 * a0 + 2], x[3 * a1 + 2]);

    int j0 = s * CH;
    int j1 = min(M, j0 + CH);
    float m0 = 3.4e38f, m1 = 3.4e38f;

    #pragma unroll 4
    for (int j = j0; j < j1; ++j) {
        float4 yv = y4[j];
        ull dx = add2(xx, pk2(yv.x, yv.x));
        ull dy = add2(xy, pk2(yv.y, yv.y));
        ull dz = add2(xz, pk2(yv.z, yv.z));
        ull d2 = mul2(dx, dx);
        d2 = fma2(dy, dy, d2);
        d2 = fma2(dz, dz, d2);
        float d20, d21; upk2(d2, d20, d21);
        m0 = fminf(m0, d20);
        m1 = fminf(m1, d21);
    }
    if (i0 < N) pmin[(size_t)s * N + i0] = m0;
    if (i1 < N) pmin[(size_t)s * N + i1] = m1;
}

// ---- k_acc: partial softmax numerator/denominator --------------------------
__global__ void __launch_bounds__(TPB) k_acc(
    const float* __restrict__ x,
    const ulonglong2* __restrict__ fea,   // M rows x 4 x ulonglong2 (= 16 floats)
    long long off_y4, long long off_pmin, long long off_ps, long long off_pacc,
    int N, int M, int CH)
{
    const float Cc = -72.13475204444817f;  // -log2(e) / (2 * 0.1^2)

    const float4* __restrict__ y4 = reinterpret_cast<const float4*>(g_scratch + off_y4);
    const float* __restrict__ pmin = g_scratch + off_pmin;
    float* __restrict__ ps   = g_scratch + off_ps;
    float* __restrict__ pacc = g_scratch + off_pacc;

    int s  = blockIdx.x % SPL;
    int qb = blockIdx.x / SPL;
    int i0 = (qb * TPB + threadIdx.x) * QPT;
    int i1 = i0 + 1;
    int a0 = min(i0, N - 1), a1 = min(i1, N - 1);

    ull xx = pk2(x[3 * a0],     x[3 * a1]);
    ull xy = pk2(x[3 * a0 + 1], x[3 * a1 + 1]);
    ull xz = pk2(x[3 * a0 + 2], x[3 * a1 + 2]);

    // global min d2 per query (reduce the SPL partials)
    float md0 = 3.4e38f, md1 = 3.4e38f;
    #pragma unroll
    for (int sp = 0; sp < SPL; ++sp) {
        md0 = fminf(md0, pmin[(size_t)sp * N + a0]);
        md1 = fminf(md1, pmin[(size_t)sp * N + a1]);
    }
    ull C2 = pk2(Cc, Cc);
    ull K2 = pk2(-Cc * md0, -Cc * md1);   // arg = C*d2 + K = C*(d2 - mind) <= 0

    ull acc0[8], acc1[8];
    #pragma unroll
    for (int k = 0; k < 8; ++k) { acc0[k] = 0ull; acc1[k] = 0ull; }
    float s0 = 0.0f, s1 = 0.0f;

    int j0 = s * CH;
    int j1 = min(M, j0 + CH);

    #pragma unroll 2
    for (int j = j0; j < j1; ++j) {
        float4 yv = y4[j];
        // identical d2 sequence to k_min -> arg <= 0 bitwise-guaranteed
        ull dx = add2(xx, pk2(yv.x, yv.x));
        ull dy = add2(xy, pk2(yv.y, yv.y));
        ull dz = add2(xz, pk2(yv.z, yv.z));
        ull d2 = mul2(dx, dx);
        d2 = fma2(dy, dy, d2);
        d2 = fma2(dz, dz, d2);
        ull arg = fma2(d2, C2, K2);
        float g0, g1; upk2(arg, g0, g1);
        float p0 = ex2(g0);
        float p1 = ex2(g1);
        s0 += p0;
        s1 += p1;
        ull pp0 = pk2(p0, p0);
        ull pp1 = pk2(p1, p1);

        const ulonglong2* fr = fea + (size_t)j * 4;
        ulonglong2 f0 = fr[0];
        ulonglong2 f1 = fr[1];
        ulonglong2 f2 = fr[2];
        ulonglong2 f3 = fr[3];
        acc0[0] = fma2(pp0, f0.x, acc0[0]);  acc1[0] = fma2(pp1, f0.x, acc1[0]);
        acc0[1] = fma2(pp0, f0.y, acc0[1]);  acc1[1] = fma2(pp1, f0.y, acc1[1]);
        acc0[2] = fma2(pp0, f1.x, acc0[2]);  acc1[2] = fma2(pp1, f1.x, acc1[2]);
        acc0[3] = fma2(pp0, f1.y, acc0[3]);  acc1[3] = fma2(pp1, f1.y, acc1[3]);
        acc0[4] = fma2(pp0, f2.x, acc0[4]);  acc1[4] = fma2(pp1, f2.x, acc1[4]);
        acc0[5] = fma2(pp0, f2.y, acc0[5]);  acc1[5] = fma2(pp1, f2.y, acc1[5]);
        acc0[6] = fma2(pp0, f3.x, acc0[6]);  acc1[6] = fma2(pp1, f3.x, acc1[6]);
        acc0[7] = fma2(pp0, f3.y, acc0[7]);  acc1[7] = fma2(pp1, f3.y, acc1[7]);
    }

    if (i0 < N) {
        ps[(size_t)s * N + i0] = s0;
        float4* dst = reinterpret_cast<float4*>(pacc + ((size_t)s * N + i0) * DD);
        #pragma unroll
        for (int k = 0; k < 4; ++k) {
            float lo0, hi0, lo1, hi1;
            upk2(acc0[2 * k],     lo0, hi0);
            upk2(acc0[2 * k + 1], lo1, hi1);
            dst[k] = make_float4(lo0, hi0, lo1, hi1);
        }
    }
    if (i1 < N) {
        ps[(size_t)s * N + i1] = s1;
        float4* dst = reinterpret_cast<float4*>(pacc + ((size_t)s * N + i1) * DD);
        #pragma unroll
        for (int k = 0; k < 4; ++k) {
            float lo0, hi0, lo1, hi1;
            upk2(acc1[2 * k],     lo0, hi0);
            upk2(acc1[2 * k + 1], lo1, hi1);
            dst[k] = make_float4(lo0, hi0, lo1, hi1);
        }
    }
}

// ---- k_norm: reduce over splits and normalize ------------------------------
__global__ void k_norm(long long off_ps, long long off_pacc,
                       float* __restrict__ out, int N)
{
    const float* __restrict__ ps   = g_scratch + off_ps;
    const float* __restrict__ pacc = g_scratch + off_pacc;
    int idx = blockIdx.x * blockDim.x + threadIdx.x;
    if (idx >= N * DD) return;
    int i = idx / DD;
    int d = idx % DD;
    float st = 0.0f, at = 0.0f;
    #pragma unroll
    for (int sp = 0; sp < SPL; ++sp) {
        st += ps[(size_t)sp * N + i];
        at += pacc[((size_t)sp * N + i) * DD + d];
    }
    out[idx] = at / st;
}

// ---------------------------------------------------------------------------
extern "C" void kernel_launch(void* const* d_in, const int* in_sizes, int n_in,
                              void* d_out, int out_size) {
    const float* x   = (const float*)d_in[0];   // [N,3]
    const float* y   = (const float*)d_in[1];   // [M,3]
    const float* fea = (const float*)d_in[2];   // [M,16]
    float* out = (float*)d_out;                 // [N,16]

    int N = in_sizes[0] / 3;
    int M = in_sizes[1] / 3;

    auto r4 = [](long long v) { return (v + 3) & ~3LL; };
    long long off_y4   = 0;
    long long off_pmin = r4(off_y4 + 4LL * M);
    long long off_ps   = r4(off_pmin + (long long)SPL * N);
    long long off_pacc = r4(off_ps + (long long)SPL * N);
    // total: 4M + 2*SPL*N + SPL*N*16  ~= 5.4M floats < 8M capacity

    int CH = (M + SPL - 1) / SPL;                 // j-chunk per split (512)
    int QB = (N + TPB * QPT - 1) / (TPB * QPT);   // query blocks (48)

    k_prep<<<(M + 255) / 256, 256>>>(y, off_y4, M);
    k_min<<<QB * SPL, TPB>>>(x, off_y4, off_pmin, N, M, CH);
    k_acc<<<QB * SPL, TPB>>>(x, (const ulonglong2*)fea,
                             off_y4, off_pmin, off_ps, off_pacc, N, M, CH);
    k_norm<<<(N * DD + 255) / 256, 256>>>(off_ps, off_pacc, out, N);
}